// round 2
// baseline (speedup 1.0000x reference)
#include <cuda_runtime.h>
#include <cuda_fp16.h>
#include <math.h>

#define BATCH 32
#define HH 1024
#define WW 1024
#define HS 128            // rows per pass2 block

// 64 MB scratch: horizontal 31-tap box sums in fp16 (values in [0,31])
__device__ __half2 g_hsum[BATCH * HH * (WW / 2)];
__device__ double g_bce;
__device__ double g_inter[BATCH];
__device__ double g_union[BATCH];

__global__ void init_kernel() {
    int t = threadIdx.x;
    if (t == 0) g_bce = 0.0;
    if (t < BATCH) { g_inter[t] = 0.0; g_union[t] = 0.0; }
}

// Horizontal 31-tap box sum via per-row prefix scan. One 256-thread block per row.
// hsum[x] = pref(x+15) - pref(x-16)  (zero pad outside [0,1024)), stored as fp16.
__global__ void __launch_bounds__(256) hsum_kernel(const float* __restrict__ tgt) {
    const int row = blockIdx.x;                    // 0 .. BATCH*HH-1
    const float* src = tgt + (size_t)row * WW;
    __half2* dst = g_hsum + (size_t)row * (WW / 2);

    __shared__ float PS[WW + 32];                  // PS[16+x] = pref(0..x); guards both sides
    __shared__ float warpTot[8];
    const int tid = threadIdx.x;

    float4 v = reinterpret_cast<const float4*>(src)[tid];
    float s0 = v.x;
    float s1 = s0 + v.y;
    float s2 = s1 + v.z;
    float s3 = s2 + v.w;
    float csum = s3;

    // inclusive warp scan over per-thread chunk sums
    float ws = csum;
    #pragma unroll
    for (int d = 1; d < 32; d <<= 1) {
        float n = __shfl_up_sync(0xffffffffu, ws, d);
        if ((tid & 31) >= d) ws += n;
    }
    if ((tid & 31) == 31) warpTot[tid >> 5] = ws;
    __syncthreads();

    float base = ws - csum;                        // exclusive within warp
    const int wid = tid >> 5;
    #pragma unroll
    for (int w = 0; w < 8; ++w)
        if (w < wid) base += warpTot[w];

    PS[16 + 4 * tid + 0] = base + s0;
    PS[16 + 4 * tid + 1] = base + s1;
    PS[16 + 4 * tid + 2] = base + s2;
    PS[16 + 4 * tid + 3] = base + s3;
    if (tid < 16) {
        PS[tid] = 0.0f;                            // pref(<0) = 0
        float total = 0.f;
        #pragma unroll
        for (int w = 0; w < 8; ++w) total += warpTot[w];
        PS[16 + WW + tid] = total;                 // pref(>=W) = total
    }
    __syncthreads();

    // hsum[x] = PS[x+31] - PS[x]; pack pairs into half2
    #pragma unroll
    for (int k = 0; k < 2; ++k) {
        const int p = tid + 256 * k;               // half2 index 0..511
        const int x = 2 * p;
        const float a = PS[x + 31] - PS[x];
        const float b = PS[x + 32] - PS[x + 1];
        dst[p] = __floats2half2_rn(a, b);
    }
}

// Per-pixel fused math
__device__ __forceinline__ void px(float xv, float tv, float vs,
                                   float& bceA, float& intA, float& uniA) {
    const float avg  = vs * (1.0f / 961.0f);
    const float weit = 1.0f + 5.0f * fabsf(avg - tv);
    const float ax   = fabsf(xv);
    const float e    = __expf(-ax);                 // exp(-|x|)
    const float bce  = fmaxf(xv, 0.0f) - xv * tv + log1pf(e);
    const float r    = 1.0f / (1.0f + e);
    const float p    = (xv >= 0.0f) ? r : e * r;    // sigmoid via shared e
    bceA += bce;
    intA += p * tv * weit;
    uniA += (p + tv) * weit;
}

// Vertical running box sum fused with all elementwise math + reductions.
// 256 threads x 2 columns (half2/float2) = 512-column strip, HS rows.
__global__ void __launch_bounds__(256) pass2_kernel(const float2* __restrict__ inp,
                                                    const float2* __restrict__ tgt) {
    const int b   = blockIdx.z;
    const int c2  = blockIdx.x * 256 + threadIdx.x;   // half2 / float2 column index
    const int y0  = blockIdx.y * HS;
    const size_t img2 = (size_t)b * HH * (WW / 2);
    const __half2* Hp = g_hsum + img2;
    const float2*  T  = tgt + img2;
    const float2*  X  = inp + img2;
    const int RS = WW / 2;                            // row stride in vec2 units

    // warm-up: vertical window sum for row y0 (rows y0-15 .. y0+15)
    float2 vacc = make_float2(0.f, 0.f);
    #pragma unroll
    for (int yy = y0 - 15; yy <= y0 + 15; ++yy)
        if (yy >= 0 && yy < HH) {
            const float2 h = __half22float2(Hp[(size_t)yy * RS + c2]);
            vacc.x += h.x; vacc.y += h.y;
        }

    float bceA = 0.f, intA = 0.f, uniA = 0.f;
    #pragma unroll 2
    for (int y = y0; y < y0 + HS; ++y) {
        const size_t idx = (size_t)y * RS + c2;
        const float2 tv = T[idx];
        const float2 xv = X[idx];
        px(xv.x, tv.x, vacc.x, bceA, intA, uniA);
        px(xv.y, tv.y, vacc.y, bceA, intA, uniA);
        // slide window: y -> y+1
        const int ya = y + 16, yr = y - 15;
        float2 add = make_float2(0.f, 0.f), rem = make_float2(0.f, 0.f);
        if (ya < HH) add = __half22float2(Hp[(size_t)ya * RS + c2]);
        if (yr >= 0) rem = __half22float2(Hp[(size_t)yr * RS + c2]);
        vacc.x += add.x - rem.x;
        vacc.y += add.y - rem.y;
    }

    // block reduction (warp shuffles + smem), then double atomics
    #pragma unroll
    for (int o = 16; o > 0; o >>= 1) {
        bceA += __shfl_down_sync(0xffffffffu, bceA, o);
        intA += __shfl_down_sync(0xffffffffu, intA, o);
        uniA += __shfl_down_sync(0xffffffffu, uniA, o);
    }
    __shared__ float red[3][8];
    const int wid = threadIdx.x >> 5, lane = threadIdx.x & 31;
    if (lane == 0) { red[0][wid] = bceA; red[1][wid] = intA; red[2][wid] = uniA; }
    __syncthreads();
    if (threadIdx.x == 0) {
        double rb = 0, ri = 0, ru = 0;
        #pragma unroll
        for (int w = 0; w < 8; ++w) { rb += red[0][w]; ri += red[1][w]; ru += red[2][w]; }
        atomicAdd(&g_bce, rb);
        atomicAdd(&g_inter[b], ri);
        atomicAdd(&g_union[b], ru);
    }
}

// Parallel finalize: one batch per lane, DDIVs in parallel, warp-reduce doubles.
__global__ void finalize_kernel(float* out, int n) {
    const int b = threadIdx.x;                       // 32 threads
    const double inter = g_inter[b];
    const double uni   = g_union[b];
    double wiou = 1.0 - (inter + 1.0) / (uni - inter + 1.0);
    #pragma unroll
    for (int o = 16; o > 0; o >>= 1)
        wiou += __shfl_down_sync(0xffffffffu, wiou, o);
    if (b == 0) {
        const double bce = g_bce / (double)((size_t)BATCH * HH * WW);
        // wbce == bce exactly (scalar factors out of weighted mean)
        const float r = (float)(bce + wiou / (double)BATCH);
        for (int i = 0; i < n; ++i) out[i] = r;
    }
}

extern "C" void kernel_launch(void* const* d_in, const int* in_sizes, int n_in,
                              void* d_out, int out_size) {
    const float* inp = (const float*)d_in[0];   // "input"
    const float* tgt = (const float*)d_in[1];   // "target"
    float* out = (float*)d_out;

    init_kernel<<<1, 64>>>();
    hsum_kernel<<<BATCH * HH, 256>>>(tgt);
    dim3 g2(WW / 512, HH / HS, BATCH);
    pass2_kernel<<<g2, 256>>>((const float2*)inp, (const float2*)tgt);
    finalize_kernel<<<1, 32>>>(out, out_size);
}

// round 3
// speedup vs baseline: 2.1047x; 2.1047x over previous
#include <cuda_runtime.h>
#include <cuda_fp16.h>
#include <math.h>

#define BATCH 32
#define HH 1024
#define WW 1024
#define HS 128                      // output rows per block
#define RING_BYTES (31 * WW * 2)    // 31-row fp16 ring: 63488 B
#define PS_FLOATS  (WW + 32)        // prefix array with 16-guard each side
#define SMEM_BYTES (RING_BYTES + PS_FLOATS * 4 + 128)

__device__ double g_bce;
__device__ double g_inter[BATCH];
__device__ double g_union[BATCH];

__global__ void init_kernel() {
    int t = threadIdx.x;
    if (t == 0) g_bce = 0.0;
    if (t < BATCH) { g_inter[t] = 0.0; g_union[t] = 0.0; }
}

// Fused per-pixel math (fast intrinsics: ~2 ulp, irrelevant vs 1e-3 gate)
__device__ __forceinline__ void px(float xv, float tv, float vs,
                                   float& bceA, float& intA, float& uniA) {
    const float avg  = vs * (1.0f / 961.0f);
    const float weit = fmaf(5.0f, fabsf(avg - tv), 1.0f);
    const float ax   = fabsf(xv);
    const float e    = __expf(-ax);                  // exp(-|x|)
    const float bce  = fmaxf(xv, 0.0f) - xv * tv + __logf(1.0f + e);
    const float inv  = __fdividef(1.0f, 1.0f + e);
    const float p    = (xv >= 0.0f) ? inv : e * inv; // sigmoid
    bceA += bce;
    intA += p * tv * weit;
    uniA += (p + tv) * weit;
}

extern __shared__ char smem_raw[];

// One block per (128-row strip, batch). Streams rows: horizontal 31-sum by
// prefix scan, 31-row fp16 smem ring for the vertical window, emit 15 rows
// behind the scan front with fused math + block reduction.
__global__ void __launch_bounds__(256) fused_kernel(const float4* __restrict__ inp,
                                                    const float4* __restrict__ tgt) {
    __half2* ring = reinterpret_cast<__half2*>(smem_raw);            // 31 x 512 half2
    float*   PS   = reinterpret_cast<float*>(smem_raw + RING_BYTES); // PS[16+x]=pref(0..x)
    float*   wtot = PS + PS_FLOATS;                                  // 8 floats
    __shared__ float red[3][8];

    const int tid  = threadIdx.x;
    const int lane = tid & 31, wid = tid >> 5;
    const int y0   = blockIdx.x * HS;
    const int b    = blockIdx.y;
    const size_t img = (size_t)b * HH * (WW / 4);
    const float4* T = tgt + img;
    const float4* X = inp + img;
    const int RS = WW / 4;                                           // row stride (float4)

    float4 vacc = make_float4(0.f, 0.f, 0.f, 0.f);
    float bceA = 0.f, intA = 0.f, uniA = 0.f;

    const int rbeg = y0 - 15;
    const int rend = y0 + HS + 14;                                   // inclusive
    float4 vnext = make_float4(0.f, 0.f, 0.f, 0.f);
    if (rbeg >= 0) vnext = T[(size_t)rbeg * RS + tid];
    int slot = 0;

    for (int r = rbeg; r <= rend; ++r) {
        const float4 v = vnext;
        const int rn = r + 1;
        if (rn < HH && rn <= rend) vnext = T[(size_t)rn * RS + tid]; // prefetch scan row
        else vnext = make_float4(0.f, 0.f, 0.f, 0.f);

        const int y = r - 15;                                        // emit row
        const bool emit = (y >= y0);
        float4 xv = make_float4(0.f, 0.f, 0.f, 0.f);
        float4 tv = make_float4(0.f, 0.f, 0.f, 0.f);
        if (emit) {                                                  // prefetch emit rows
            xv = X[(size_t)y * RS + tid];
            tv = T[(size_t)y * RS + tid];                            // L1/L2 hit (15 rows stale)
        }

        // horizontal 31-tap sum of row r via block prefix scan (r uniform -> syncs uniform)
        float4 h = make_float4(0.f, 0.f, 0.f, 0.f);
        const int x = 4 * tid;
        if (r >= 0 && r < HH) {
            const float s0 = v.x, s1 = s0 + v.y, s2 = s1 + v.z, s3 = s2 + v.w;
            float ws = s3;
            #pragma unroll
            for (int d = 1; d < 32; d <<= 1) {
                float n = __shfl_up_sync(0xffffffffu, ws, d);
                if (lane >= d) ws += n;
            }
            if (lane == 31) wtot[wid] = ws;
            __syncthreads();
            float base = ws - s3;
            #pragma unroll
            for (int w = 0; w < 8; ++w)
                if (w < wid) base += wtot[w];
            PS[16 + x + 0] = base + s0;
            PS[16 + x + 1] = base + s1;
            PS[16 + x + 2] = base + s2;
            PS[16 + x + 3] = base + s3;
            if (tid < 16) {
                PS[tid] = 0.0f;                                      // pref(<0)=0
                float tot = 0.f;
                #pragma unroll
                for (int w = 0; w < 8; ++w) tot += wtot[w];
                PS[16 + WW + tid] = tot;                             // pref(>=W)=total
            }
            __syncthreads();
            h.x = PS[x + 31] - PS[x];                                // pref(x+15)-pref(x-16)
            h.y = PS[x + 32] - PS[x + 1];
            h.z = PS[x + 33] - PS[x + 2];
            h.w = PS[x + 34] - PS[x + 3];
        }

        // vertical sliding window via fp16 ring (thread-private columns, no sync needed)
        __half2* rrow = ring + slot * (WW / 2);
        const __half2 oldA = rrow[2 * tid];
        const __half2 oldB = rrow[2 * tid + 1];
        rrow[2 * tid]     = __floats2half2_rn(h.x, h.y);
        rrow[2 * tid + 1] = __floats2half2_rn(h.z, h.w);
        if (r >= y0 + 16) {                                          // slot == slot(r-31)
            const float2 oa = __half22float2(oldA);
            const float2 ob = __half22float2(oldB);
            vacc.x += h.x - oa.x; vacc.y += h.y - oa.y;
            vacc.z += h.z - ob.x; vacc.w += h.w - ob.y;
        } else {
            vacc.x += h.x; vacc.y += h.y; vacc.z += h.z; vacc.w += h.w;
        }
        slot = (slot == 30) ? 0 : slot + 1;

        if (emit) {
            px(xv.x, tv.x, vacc.x, bceA, intA, uniA);
            px(xv.y, tv.y, vacc.y, bceA, intA, uniA);
            px(xv.z, tv.z, vacc.z, bceA, intA, uniA);
            px(xv.w, tv.w, vacc.w, bceA, intA, uniA);
        }
    }

    // block reduction -> double atomics
    #pragma unroll
    for (int o = 16; o > 0; o >>= 1) {
        bceA += __shfl_down_sync(0xffffffffu, bceA, o);
        intA += __shfl_down_sync(0xffffffffu, intA, o);
        uniA += __shfl_down_sync(0xffffffffu, uniA, o);
    }
    if (lane == 0) { red[0][wid] = bceA; red[1][wid] = intA; red[2][wid] = uniA; }
    __syncthreads();
    if (tid == 0) {
        double rb = 0, ri = 0, ru = 0;
        #pragma unroll
        for (int w = 0; w < 8; ++w) { rb += red[0][w]; ri += red[1][w]; ru += red[2][w]; }
        atomicAdd(&g_bce, rb);
        atomicAdd(&g_inter[b], ri);
        atomicAdd(&g_union[b], ru);
    }
}

// Parallel finalize: one batch per lane, DDIVs in parallel, warp-reduce doubles.
__global__ void finalize_kernel(float* out, int n) {
    const int b = threadIdx.x;                       // 32 threads
    const double inter = g_inter[b];
    const double uni   = g_union[b];
    double wiou = 1.0 - (inter + 1.0) / (uni - inter + 1.0);
    #pragma unroll
    for (int o = 16; o > 0; o >>= 1)
        wiou += __shfl_down_sync(0xffffffffu, wiou, o);
    if (b == 0) {
        const double bce = g_bce / (double)((size_t)BATCH * HH * WW);
        // wbce == bce exactly (scalar factors out of the weighted mean)
        const float r = (float)(bce + wiou / (double)BATCH);
        for (int i = 0; i < n; ++i) out[i] = r;
    }
}

extern "C" void kernel_launch(void* const* d_in, const int* in_sizes, int n_in,
                              void* d_out, int out_size) {
    const float* inp = (const float*)d_in[0];   // "input"
    const float* tgt = (const float*)d_in[1];   // "target"
    float* out = (float*)d_out;

    cudaFuncSetAttribute(fused_kernel,
                         cudaFuncAttributeMaxDynamicSharedMemorySize, SMEM_BYTES);
    init_kernel<<<1, 64>>>();
    fused_kernel<<<dim3(HH / HS, BATCH), 256, SMEM_BYTES>>>(
        (const float4*)inp, (const float4*)tgt);
    finalize_kernel<<<1, 32>>>(out, out_size);
}